// round 15
// baseline (speedup 1.0000x reference)
#include <cuda_runtime.h>
#include <math.h>

// ----------------------------------------------------------------------------
// LlamaBlock: B=8, M=1024, D=512, H=8, fp32.
// Pipeline:
//   rms1 -> xn -> QKV gemm (fused 8192x12288x512) -> rope(q*1/sqrt(512), k)
//   -> scores gemm (batched 64x: 1024x1024x512) -> softmax -> ctx gemm (PV)
//   -> Wo gemm (+bo, +xn residual, in-place -> x2) -> rms2 -> x3
//   -> ffn gemms (Wff,+bff / Wg,+bg / Wl,+bl) -> swiglu + residual -> out
// All GEMMs: 128x128 block tile, BK=8, 8x8 per-thread microtile, 256 threads.
// ----------------------------------------------------------------------------

// ---------------- scratch (device globals; no runtime allocation) -----------
__device__ float  g_xn [4194304];    // xn, then x2 (in-place)
__device__ float  g_x3 [4194304];
__device__ float  g_h1 [4194304];
__device__ float  g_g  [4194304];
__device__ float  g_l  [4194304];
__device__ float  g_q  [33554432];   // [h][b][m][o]
__device__ float  g_k  [33554432];
__device__ float  g_v  [33554432];
__device__ float  g_ctx[33554432];   // [h][b][m][o]
__device__ float  g_s  [67108864];   // [hb][m][m] scores / probs
__device__ float2 g_cs [262144];     // rope cos/sin table [m][i]
__device__ float  g_part[512];
__device__ float  g_inv [8];

// ---------------- GEMM tile-fill / epilogue functors ------------------------
// All GEMMs compute C[r,n] = sum_k A[r,k] * B[n,k]  (TN form) unless FillNN.

struct FillTN {                 // operand stored [T][K], K contiguous
    const float* base; int ld; size_t zs;
    __device__ void setz(int z) { base += zs * (size_t)z; }
    __device__ void fill(float (*S)[128], int t0, int k0, int tid) {
        int r = tid >> 1, c = (tid & 1) * 4;
        float4 v = *(const float4*)(base + (size_t)(t0 + r) * ld + k0 + c);
        S[c+0][r] = v.x; S[c+1][r] = v.y; S[c+2][r] = v.z; S[c+3][r] = v.w;
    }
};

struct FillNN {                 // B stored [K][N], N contiguous (for P@V)
    const float* base; int ld; size_t zs;
    __device__ void setz(int z) { base += zs * (size_t)z; }
    __device__ void fill(float (*S)[128], int t0, int k0, int tid) {
        int r = tid >> 5, c = (tid & 31) * 4;
        float4 v = *(const float4*)(base + (size_t)(k0 + r) * ld + t0 + c);
        *(float4*)&S[r][c] = v;
    }
};

struct FillQKVW {               // B rows 0..12287 span Wq|Wk|Wv, each (4096x512)
    const float* wq; const float* wk; const float* wv;
    __device__ void setz(int) {}
    __device__ void fill(float (*S)[128], int t0, int k0, int tid) {
        int r = tid >> 1, c = (tid & 1) * 4;
        int sect = t0 >> 12;
        const float* w = (sect == 0) ? wq : (sect == 1 ? wk : wv);
        int nl = (t0 & 4095) + r;
        float4 v = *(const float4*)(w + (size_t)nl * 512 + k0 + c);
        S[c+0][r] = v.x; S[c+1][r] = v.y; S[c+2][r] = v.z; S[c+3][r] = v.w;
    }
};

struct FillCat {                // A[r,kk] = ctx[(kk>>9)][r][kk&511]  (cat view)
    const float* base;
    __device__ void setz(int) {}
    __device__ void fill(float (*S)[128], int t0, int k0, int tid) {
        int r = tid >> 1, c = (tid & 1) * 4;
        int kk = k0 + c;
        const float* p = base + (size_t)(kk >> 9) * 4194304
                              + (size_t)(t0 + r) * 512 + (kk & 511);
        float4 v = *(const float4*)p;
        S[c+0][r] = v.x; S[c+1][r] = v.y; S[c+2][r] = v.z; S[c+3][r] = v.w;
    }
};

struct EpiStore {
    float* C; int ldc; size_t zs;
    __device__ void setz(int z) { C += zs * (size_t)z; }
    __device__ void store(int r, int n, float v) { C[(size_t)r * ldc + n] = v; }
};

struct EpiBias {
    float* C; const float* bias; int ldc;
    __device__ void setz(int) {}
    __device__ void store(int r, int n, float v) {
        C[(size_t)r * ldc + n] = v + bias[n];
    }
};

struct EpiQKV {                 // scatter col n -> q/k/v [h][b][m][o]
    float* q; float* k; float* v;
    __device__ void setz(int) {}
    __device__ void store(int r, int n, float val) {
        float* out = (n < 4096) ? q : (n < 8192 ? k : v);
        int nl = n & 4095;
        out[(size_t)(nl >> 9) * 4194304 + (size_t)r * 512 + (nl & 511)] = val;
    }
};

struct EpiWo {                  // x2 = attn_out + bo + xn   (in-place over xn)
    float* x2; const float* bo;
    __device__ void setz(int) {}
    __device__ void store(int r, int n, float v) {
        size_t i = (size_t)r * 512 + n;
        x2[i] = v + bo[n] + x2[i];
    }
};

// ---------------- generic 128x128x8 SGEMM -----------------------------------
template <class FA, class FB, class EPI>
__global__ __launch_bounds__(256) void gemm128(FA fa, FB fb, EPI epi, int K) {
    __shared__ __align__(16) float As[8][128];
    __shared__ __align__(16) float Bs[8][128];
    const int tid = threadIdx.x;
    const int m0 = blockIdx.y * 128;
    const int n0 = blockIdx.x * 128;
    fa.setz(blockIdx.z); fb.setz(blockIdx.z); epi.setz(blockIdx.z);

    const int ty = tid >> 4;   // 0..15
    const int tx = tid & 15;   // 0..15

    float acc[8][8] = {};

    for (int k0 = 0; k0 < K; k0 += 8) {
        fa.fill(As, m0, k0, tid);
        fb.fill(Bs, n0, k0, tid);
        __syncthreads();
#pragma unroll
        for (int kk = 0; kk < 8; kk++) {
            float a[8], b[8];
            *(float4*)(a)     = *(const float4*)&As[kk][ty * 4];
            *(float4*)(a + 4) = *(const float4*)&As[kk][ty * 4 + 64];
            *(float4*)(b)     = *(const float4*)&Bs[kk][tx * 4];
            *(float4*)(b + 4) = *(const float4*)&Bs[kk][tx * 4 + 64];
#pragma unroll
            for (int i = 0; i < 8; i++)
#pragma unroll
                for (int j = 0; j < 8; j++)
                    acc[i][j] += a[i] * b[j];
        }
        __syncthreads();
    }

#pragma unroll
    for (int i = 0; i < 8; i++) {
        int r = m0 + ty * 4 + ((i < 4) ? i : (60 + i));
#pragma unroll
        for (int j = 0; j < 8; j++) {
            int n = n0 + tx * 4 + ((j < 4) ? j : (60 + j));
            epi.store(r, n, acc[i][j]);
        }
    }
}

// ---------------- elementwise / reduction kernels ---------------------------
__global__ void reduce_sq_k(const float* __restrict__ x, float* __restrict__ part) {
    __shared__ float red[256];
    int t = threadIdx.x;
    const float4* p = (const float4*)(x + (size_t)blockIdx.y * 524288
                                        + (size_t)blockIdx.x * 8192);
    float s = 0.f;
#pragma unroll
    for (int i = 0; i < 8; i++) {
        float4 v = p[t + i * 256];
        s += v.x * v.x + v.y * v.y + v.z * v.z + v.w * v.w;
    }
    red[t] = s; __syncthreads();
    for (int st = 128; st > 0; st >>= 1) {
        if (t < st) red[t] += red[t + st];
        __syncthreads();
    }
    if (t == 0) part[blockIdx.y * 64 + blockIdx.x] = red[0];
}

__global__ void finalize_rms_k(const float* __restrict__ part, float* __restrict__ inv) {
    __shared__ float red[64];
    int t = threadIdx.x;
    red[t] = part[blockIdx.x * 64 + t]; __syncthreads();
    for (int st = 32; st > 0; st >>= 1) {
        if (t < st) red[t] += red[t + st];
        __syncthreads();
    }
    // inv = 1/ff_rms = sqrt(M*D / sum(x^2))
    if (t == 0) inv[blockIdx.x] = sqrtf(524288.0f / red[0]);
}

__global__ void rmsnorm_k(const float* __restrict__ in, const float* __restrict__ scale,
                          const float* __restrict__ inv, float* __restrict__ out) {
    size_t i4 = (size_t)blockIdx.x * 256 + threadIdx.x;     // float4 index
    float iv = inv[(int)(i4 >> 17)];                        // 131072 float4 / batch
    float4 xv = ((const float4*)in)[i4];
    float4 sv = ((const float4*)scale)[i4 & 131071];
    float4 o;
    o.x = xv.x * sv.x * iv; o.y = xv.y * sv.y * iv;
    o.z = xv.z * sv.z * iv; o.w = xv.w * sv.w * iv;
    ((float4*)out)[i4] = o;
}

__global__ void rope_table_k(float2* __restrict__ cs) {
    int idx = blockIdx.x * 256 + threadIdx.x;               // 1024*256
    int m = idx >> 8, i = idx & 255;
    float e = -2.0f * ((float)i - 1.0f) / 512.0f;           // NB: (i-1) per reference
    float th = powf(10000.0f, e);
    float ang = (float)m * th;
    float s, c;
    sincosf(ang, &s, &c);
    cs[idx] = make_float2(c, s);
}

__global__ void rope_apply_k(float2* __restrict__ t, const float2* __restrict__ cs,
                             float sc) {
    size_t idx = (size_t)blockIdx.x * 256 + threadIdx.x;    // pair index
    float2 v = t[idx];
    float2 w = cs[idx & 262143];                            // (m*256 + i)
    float re = (v.x * w.x + v.y * w.y) * sc;
    float ro = (v.y * w.x - v.x * w.y) * sc;
    t[idx] = make_float2(re, ro);
}

__global__ void softmax_k(float* __restrict__ S) {
    __shared__ float red[256];
    int t = threadIdx.x;
    float4* p = (float4*)(S + (size_t)blockIdx.x * 1024);
    float4 x = p[t];
    float mx = fmaxf(fmaxf(x.x, x.y), fmaxf(x.z, x.w));
    red[t] = mx; __syncthreads();
    for (int st = 128; st > 0; st >>= 1) {
        if (t < st) red[t] = fmaxf(red[t], red[t + st]);
        __syncthreads();
    }
    mx = red[0]; __syncthreads();
    float4 e;
    e.x = expf(x.x - mx); e.y = expf(x.y - mx);
    e.z = expf(x.z - mx); e.w = expf(x.w - mx);
    red[t] = e.x + e.y + e.z + e.w; __syncthreads();
    for (int st = 128; st > 0; st >>= 1) {
        if (t < st) red[t] += red[t + st];
        __syncthreads();
    }
    float rinv = 1.f / red[0];
    e.x *= rinv; e.y *= rinv; e.z *= rinv; e.w *= rinv;
    p[t] = e;
}

__global__ void swiglu_k(const float* __restrict__ x3, const float* __restrict__ g,
                         const float* __restrict__ l, const float* __restrict__ beta,
                         float* __restrict__ out) {
    size_t i4 = (size_t)blockIdx.x * 256 + threadIdx.x;
    float bt = beta[0];
    float4 gv = ((const float4*)g)[i4];
    float4 lv = ((const float4*)l)[i4];
    float4 xv = ((const float4*)x3)[i4];
    float4 o;
    o.x = xv.x + gv.x / (1.f + expf(-bt * gv.x)) * lv.x;
    o.y = xv.y + gv.y / (1.f + expf(-bt * gv.y)) * lv.y;
    o.z = xv.z + gv.z / (1.f + expf(-bt * gv.z)) * lv.z;
    o.w = xv.w + gv.w / (1.f + expf(-bt * gv.w)) * lv.w;
    ((float4*)out)[i4] = o;
}

// ---------------- host orchestration ----------------------------------------
extern "C" void kernel_launch(void* const* d_in, const int* in_sizes, int n_in,
                              void* d_out, int out_size) {
    const float* x     = (const float*)d_in[0];
    const float* scale = (const float*)d_in[1];
    const float* Wq    = (const float*)d_in[2];
    const float* Wk    = (const float*)d_in[3];
    const float* Wv    = (const float*)d_in[4];
    const float* Wo    = (const float*)d_in[5];
    const float* bo    = (const float*)d_in[6];
    const float* Wff   = (const float*)d_in[7];
    const float* bff   = (const float*)d_in[8];
    const float* Wg    = (const float*)d_in[9];
    const float* bg    = (const float*)d_in[10];
    const float* Wl    = (const float*)d_in[11];
    const float* bl    = (const float*)d_in[12];
    const float* beta  = (const float*)d_in[13];
    float* out = (float*)d_out;

    float *xn, *x3, *h1, *gg, *ll, *q, *k, *v, *ctx, *s, *part, *inv;
    float2* cs;
    cudaGetSymbolAddress((void**)&xn,  g_xn);
    cudaGetSymbolAddress((void**)&x3,  g_x3);
    cudaGetSymbolAddress((void**)&h1,  g_h1);
    cudaGetSymbolAddress((void**)&gg,  g_g);
    cudaGetSymbolAddress((void**)&ll,  g_l);
    cudaGetSymbolAddress((void**)&q,   g_q);
    cudaGetSymbolAddress((void**)&k,   g_k);
    cudaGetSymbolAddress((void**)&v,   g_v);
    cudaGetSymbolAddress((void**)&ctx, g_ctx);
    cudaGetSymbolAddress((void**)&s,   g_s);
    cudaGetSymbolAddress((void**)&part, g_part);
    cudaGetSymbolAddress((void**)&inv,  g_inv);
    cudaGetSymbolAddress((void**)&cs,   g_cs);

    // rope table (recomputed every call; deterministic)
    rope_table_k<<<1024, 256>>>(cs);

    // rmsnorm #1 : xn = scale * x / rms_batch(x)
    reduce_sq_k<<<dim3(64, 8), 256>>>(x, part);
    finalize_rms_k<<<8, 64>>>(part, inv);
    rmsnorm_k<<<4096, 256>>>(x, scale, inv, xn);

    // fused QKV projection: C(8192 x 12288) = xn @ [Wq;Wk;Wv]^T
    gemm128<<<dim3(96, 64, 1), 256>>>(
        FillTN{xn, 512, 0}, FillQKVW{Wq, Wk, Wv}, EpiQKV{q, k, v}, 512);

    // rope (fold 1/sqrt(512) into q)
    rope_apply_k<<<65536, 256>>>((float2*)q, cs, 0.04419417382415922f);
    rope_apply_k<<<65536, 256>>>((float2*)k, cs, 1.0f);

    // scores = qr @ kr^T   (batched over 64 head-batch pairs)
    gemm128<<<dim3(8, 8, 64), 256>>>(
        FillTN{q, 512, 524288}, FillTN{k, 512, 524288},
        EpiStore{s, 1024, 1048576}, 512);

    softmax_k<<<65536, 256>>>(s);

    // ctx = P @ V
    gemm128<<<dim3(4, 8, 64), 256>>>(
        FillTN{s, 1024, 1048576}, FillNN{v, 512, 524288},
        EpiStore{ctx, 512, 524288}, 1024);

    // x2 = xn + cat(ctx) @ Wo^T + bo    (in-place into xn buffer)
    gemm128<<<dim3(4, 64, 1), 256>>>(
        FillCat{ctx}, FillTN{Wo, 4096, 0}, EpiWo{xn, bo}, 4096);

    // rmsnorm #2 : x3 = scale * x2 / rms_batch(x2)
    reduce_sq_k<<<dim3(64, 8), 256>>>(xn, part);
    finalize_rms_k<<<8, 64>>>(part, inv);
    rmsnorm_k<<<4096, 256>>>(xn, scale, inv, x3);

    // FFN
    gemm128<<<dim3(4, 64, 1), 256>>>(
        FillTN{x3, 512, 0}, FillTN{Wff, 512, 0}, EpiBias{h1, bff, 512}, 512);
    gemm128<<<dim3(4, 64, 1), 256>>>(
        FillTN{h1, 512, 0}, FillTN{Wg, 512, 0}, EpiBias{gg, bg, 512}, 512);
    gemm128<<<dim3(4, 64, 1), 256>>>(
        FillTN{h1, 512, 0}, FillTN{Wl, 512, 0}, EpiBias{ll, bl, 512}, 512);

    // out = x3 + (g * sigmoid(beta*g)) * l
    swiglu_k<<<4096, 256>>>(x3, gg, ll, beta, out);
}

// round 16
// speedup vs baseline: 1.0017x; 1.0017x over previous
#include <cuda_runtime.h>
#include <math.h>

// ----------------------------------------------------------------------------
// LlamaBlock: B=8, M=1024, D=512, H=8, fp32.
// Pipeline:
//   rms1 -> xn -> QKV gemm (fused 8192x12288x512) -> rope(q*1/sqrt(512), k)
//   -> scores gemm (batched 64x: 1024x1024x512) -> softmax -> ctx gemm (PV)
//   -> Wo gemm (+bo, +xn residual, in-place -> x2) -> rms2 -> x3
//   -> ffn gemms (Wff,+bff / Wg,+bg / Wl,+bl) -> swiglu + residual -> out
// All GEMMs: 128x128 block tile, BK=8, 8x8 per-thread microtile, 256 threads.
// ----------------------------------------------------------------------------

// ---------------- scratch (device globals; no runtime allocation) -----------
__device__ float  g_xn [4194304];    // xn, then x2 (in-place)
__device__ float  g_x3 [4194304];
__device__ float  g_h1 [4194304];
__device__ float  g_g  [4194304];
__device__ float  g_l  [4194304];
__device__ float  g_q  [33554432];   // [h][b][m][o]
__device__ float  g_k  [33554432];
__device__ float  g_v  [33554432];
__device__ float  g_ctx[33554432];   // [h][b][m][o]
__device__ float  g_s  [67108864];   // [hb][m][m] scores / probs
__device__ float2 g_cs [262144];     // rope cos/sin table [m][i]
__device__ float  g_part[512];
__device__ float  g_inv [8];

// ---------------- GEMM tile-fill / epilogue functors ------------------------
// All GEMMs compute C[r,n] = sum_k A[r,k] * B[n,k]  (TN form) unless FillNN.

struct FillTN {                 // operand stored [T][K], K contiguous
    const float* base; int ld; size_t zs;
    __device__ void setz(int z) { base += zs * (size_t)z; }
    __device__ void fill(float (*S)[128], int t0, int k0, int tid) {
        int r = tid >> 1, c = (tid & 1) * 4;
        float4 v = *(const float4*)(base + (size_t)(t0 + r) * ld + k0 + c);
        S[c+0][r] = v.x; S[c+1][r] = v.y; S[c+2][r] = v.z; S[c+3][r] = v.w;
    }
};

struct FillNN {                 // B stored [K][N], N contiguous (for P@V)
    const float* base; int ld; size_t zs;
    __device__ void setz(int z) { base += zs * (size_t)z; }
    __device__ void fill(float (*S)[128], int t0, int k0, int tid) {
        int r = tid >> 5, c = (tid & 31) * 4;
        float4 v = *(const float4*)(base + (size_t)(k0 + r) * ld + t0 + c);
        *(float4*)&S[r][c] = v;
    }
};

struct FillQKVW {               // B rows 0..12287 span Wq|Wk|Wv, each (4096x512)
    const float* wq; const float* wk; const float* wv;
    __device__ void setz(int) {}
    __device__ void fill(float (*S)[128], int t0, int k0, int tid) {
        int r = tid >> 1, c = (tid & 1) * 4;
        int sect = t0 >> 12;
        const float* w = (sect == 0) ? wq : (sect == 1 ? wk : wv);
        int nl = (t0 & 4095) + r;
        float4 v = *(const float4*)(w + (size_t)nl * 512 + k0 + c);
        S[c+0][r] = v.x; S[c+1][r] = v.y; S[c+2][r] = v.z; S[c+3][r] = v.w;
    }
};

struct FillCat {                // A[r,kk] = ctx[(kk>>9)][r][kk&511]  (cat view)
    const float* base;
    __device__ void setz(int) {}
    __device__ void fill(float (*S)[128], int t0, int k0, int tid) {
        int r = tid >> 1, c = (tid & 1) * 4;
        int kk = k0 + c;
        const float* p = base + (size_t)(kk >> 9) * 4194304
                              + (size_t)(t0 + r) * 512 + (kk & 511);
        float4 v = *(const float4*)p;
        S[c+0][r] = v.x; S[c+1][r] = v.y; S[c+2][r] = v.z; S[c+3][r] = v.w;
    }
};

struct EpiStore {
    float* C; int ldc; size_t zs;
    __device__ void setz(int z) { C += zs * (size_t)z; }
    __device__ void store(int r, int n, float v) { C[(size_t)r * ldc + n] = v; }
};

struct EpiBias {
    float* C; const float* bias; int ldc;
    __device__ void setz(int) {}
    __device__ void store(int r, int n, float v) {
        C[(size_t)r * ldc + n] = v + bias[n];
    }
};

struct EpiQKV {                 // scatter col n -> q/k/v [h][b][m][o]
    float* q; float* k; float* v;
    __device__ void setz(int) {}
    __device__ void store(int r, int n, float val) {
        float* out = (n < 4096) ? q : (n < 8192 ? k : v);
        int nl = n & 4095;
        out[(size_t)(nl >> 9) * 4194304 + (size_t)r * 512 + (nl & 511)] = val;
    }
};

struct EpiWo {                  // x2 = attn_out + bo + xn   (in-place over xn)
    float* x2; const float* bo;
    __device__ void setz(int) {}
    __device__ void store(int r, int n, float v) {
        size_t i = (size_t)r * 512 + n;
        x2[i] = v + bo[n] + x2[i];
    }
};

// ---------------- generic 128x128x8 SGEMM -----------------------------------
template <class FA, class FB, class EPI>
__global__ __launch_bounds__(256) void gemm128(FA fa, FB fb, EPI epi, int K) {
    __shared__ __align__(16) float As[8][128];
    __shared__ __align__(16) float Bs[8][128];
    const int tid = threadIdx.x;
    const int m0 = blockIdx.y * 128;
    const int n0 = blockIdx.x * 128;
    fa.setz(blockIdx.z); fb.setz(blockIdx.z); epi.setz(blockIdx.z);

    const int ty = tid >> 4;   // 0..15
    const int tx = tid & 15;   // 0..15

    float acc[8][8] = {};

    for (int k0 = 0; k0 < K; k0 += 8) {
        fa.fill(As, m0, k0, tid);
        fb.fill(Bs, n0, k0, tid);
        __syncthreads();
#pragma unroll
        for (int kk = 0; kk < 8; kk++) {
            float a[8], b[8];
            *(float4*)(a)     = *(const float4*)&As[kk][ty * 4];
            *(float4*)(a + 4) = *(const float4*)&As[kk][ty * 4 + 64];
            *(float4*)(b)     = *(const float4*)&Bs[kk][tx * 4];
            *(float4*)(b + 4) = *(const float4*)&Bs[kk][tx * 4 + 64];
#pragma unroll
            for (int i = 0; i < 8; i++)
#pragma unroll
                for (int j = 0; j < 8; j++)
                    acc[i][j] += a[i] * b[j];
        }
        __syncthreads();
    }

#pragma unroll
    for (int i = 0; i < 8; i++) {
        int r = m0 + ty * 4 + ((i < 4) ? i : (60 + i));
#pragma unroll
        for (int j = 0; j < 8; j++) {
            int n = n0 + tx * 4 + ((j < 4) ? j : (60 + j));
            epi.store(r, n, acc[i][j]);
        }
    }
}

// ---------------- elementwise / reduction kernels ---------------------------
__global__ void reduce_sq_k(const float* __restrict__ x, float* __restrict__ part) {
    __shared__ float red[256];
    int t = threadIdx.x;
    const float4* p = (const float4*)(x + (size_t)blockIdx.y * 524288
                                        + (size_t)blockIdx.x * 8192);
    float s = 0.f;
#pragma unroll
    for (int i = 0; i < 8; i++) {
        float4 v = p[t + i * 256];
        s += v.x * v.x + v.y * v.y + v.z * v.z + v.w * v.w;
    }
    red[t] = s; __syncthreads();
    for (int st = 128; st > 0; st >>= 1) {
        if (t < st) red[t] += red[t + st];
        __syncthreads();
    }
    if (t == 0) part[blockIdx.y * 64 + blockIdx.x] = red[0];
}

__global__ void finalize_rms_k(const float* __restrict__ part, float* __restrict__ inv) {
    __shared__ float red[64];
    int t = threadIdx.x;
    red[t] = part[blockIdx.x * 64 + t]; __syncthreads();
    for (int st = 32; st > 0; st >>= 1) {
        if (t < st) red[t] += red[t + st];
        __syncthreads();
    }
    // inv = 1/ff_rms = sqrt(M*D / sum(x^2))
    if (t == 0) inv[blockIdx.x] = sqrtf(524288.0f / red[0]);
}

__global__ void rmsnorm_k(const float* __restrict__ in, const float* __restrict__ scale,
                          const float* __restrict__ inv, float* __restrict__ out) {
    size_t i4 = (size_t)blockIdx.x * 256 + threadIdx.x;     // float4 index
    float iv = inv[(int)(i4 >> 17)];                        // 131072 float4 / batch
    float4 xv = ((const float4*)in)[i4];
    float4 sv = ((const float4*)scale)[i4 & 131071];
    float4 o;
    o.x = xv.x * sv.x * iv; o.y = xv.y * sv.y * iv;
    o.z = xv.z * sv.z * iv; o.w = xv.w * sv.w * iv;
    ((float4*)out)[i4] = o;
}

__global__ void rope_table_k(float2* __restrict__ cs) {
    int idx = blockIdx.x * 256 + threadIdx.x;               // 1024*256
    int m = idx >> 8, i = idx & 255;
    float e = -2.0f * ((float)i - 1.0f) / 512.0f;           // NB: (i-1) per reference
    float th = powf(10000.0f, e);
    float ang = (float)m * th;
    float s, c;
    sincosf(ang, &s, &c);
    cs[idx] = make_float2(c, s);
}

__global__ void rope_apply_k(float2* __restrict__ t, const float2* __restrict__ cs,
                             float sc) {
    size_t idx = (size_t)blockIdx.x * 256 + threadIdx.x;    // pair index
    float2 v = t[idx];
    float2 w = cs[idx & 262143];                            // (m*256 + i)
    float re = (v.x * w.x + v.y * w.y) * sc;
    float ro = (v.y * w.x - v.x * w.y) * sc;
    t[idx] = make_float2(re, ro);
}

__global__ void softmax_k(float* __restrict__ S) {
    __shared__ float red[256];
    int t = threadIdx.x;
    float4* p = (float4*)(S + (size_t)blockIdx.x * 1024);
    float4 x = p[t];
    float mx = fmaxf(fmaxf(x.x, x.y), fmaxf(x.z, x.w));
    red[t] = mx; __syncthreads();
    for (int st = 128; st > 0; st >>= 1) {
        if (t < st) red[t] = fmaxf(red[t], red[t + st]);
        __syncthreads();
    }
    mx = red[0]; __syncthreads();
    float4 e;
    e.x = expf(x.x - mx); e.y = expf(x.y - mx);
    e.z = expf(x.z - mx); e.w = expf(x.w - mx);
    red[t] = e.x + e.y + e.z + e.w; __syncthreads();
    for (int st = 128; st > 0; st >>= 1) {
        if (t < st) red[t] += red[t + st];
        __syncthreads();
    }
    float rinv = 1.f / red[0];
    e.x *= rinv; e.y *= rinv; e.z *= rinv; e.w *= rinv;
    p[t] = e;
}

__global__ void swiglu_k(const float* __restrict__ x3, const float* __restrict__ g,
                         const float* __restrict__ l, const float* __restrict__ beta,
                         float* __restrict__ out) {
    size_t i4 = (size_t)blockIdx.x * 256 + threadIdx.x;
    float bt = beta[0];
    float4 gv = ((const float4*)g)[i4];
    float4 lv = ((const float4*)l)[i4];
    float4 xv = ((const float4*)x3)[i4];
    float4 o;
    o.x = xv.x + gv.x / (1.f + expf(-bt * gv.x)) * lv.x;
    o.y = xv.y + gv.y / (1.f + expf(-bt * gv.y)) * lv.y;
    o.z = xv.z + gv.z / (1.f + expf(-bt * gv.z)) * lv.z;
    o.w = xv.w + gv.w / (1.f + expf(-bt * gv.w)) * lv.w;
    ((float4*)out)[i4] = o;
}

// ---------------- host orchestration ----------------------------------------
extern "C" void kernel_launch(void* const* d_in, const int* in_sizes, int n_in,
                              void* d_out, int out_size) {
    const float* x     = (const float*)d_in[0];
    const float* scale = (const float*)d_in[1];
    const float* Wq    = (const float*)d_in[2];
    const float* Wk    = (const float*)d_in[3];
    const float* Wv    = (const float*)d_in[4];
    const float* Wo    = (const float*)d_in[5];
    const float* bo    = (const float*)d_in[6];
    const float* Wff   = (const float*)d_in[7];
    const float* bff   = (const float*)d_in[8];
    const float* Wg    = (const float*)d_in[9];
    const float* bg    = (const float*)d_in[10];
    const float* Wl    = (const float*)d_in[11];
    const float* bl    = (const float*)d_in[12];
    const float* beta  = (const float*)d_in[13];
    float* out = (float*)d_out;

    float *xn, *x3, *h1, *gg, *ll, *q, *k, *v, *ctx, *s, *part, *inv;
    float2* cs;
    cudaGetSymbolAddress((void**)&xn,  g_xn);
    cudaGetSymbolAddress((void**)&x3,  g_x3);
    cudaGetSymbolAddress((void**)&h1,  g_h1);
    cudaGetSymbolAddress((void**)&gg,  g_g);
    cudaGetSymbolAddress((void**)&ll,  g_l);
    cudaGetSymbolAddress((void**)&q,   g_q);
    cudaGetSymbolAddress((void**)&k,   g_k);
    cudaGetSymbolAddress((void**)&v,   g_v);
    cudaGetSymbolAddress((void**)&ctx, g_ctx);
    cudaGetSymbolAddress((void**)&s,   g_s);
    cudaGetSymbolAddress((void**)&part, g_part);
    cudaGetSymbolAddress((void**)&inv,  g_inv);
    cudaGetSymbolAddress((void**)&cs,   g_cs);

    // rope table (recomputed every call; deterministic)
    rope_table_k<<<1024, 256>>>(cs);

    // rmsnorm #1 : xn = scale * x / rms_batch(x)
    reduce_sq_k<<<dim3(64, 8), 256>>>(x, part);
    finalize_rms_k<<<8, 64>>>(part, inv);
    rmsnorm_k<<<4096, 256>>>(x, scale, inv, xn);

    // fused QKV projection: C(8192 x 12288) = xn @ [Wq;Wk;Wv]^T
    gemm128<<<dim3(96, 64, 1), 256>>>(
        FillTN{xn, 512, 0}, FillQKVW{Wq, Wk, Wv}, EpiQKV{q, k, v}, 512);

    // rope (fold 1/sqrt(512) into q)
    rope_apply_k<<<65536, 256>>>((float2*)q, cs, 0.04419417382415922f);
    rope_apply_k<<<65536, 256>>>((float2*)k, cs, 1.0f);

    // scores = qr @ kr^T   (batched over 64 head-batch pairs)
    gemm128<<<dim3(8, 8, 64), 256>>>(
        FillTN{q, 512, 524288}, FillTN{k, 512, 524288},
        EpiStore{s, 1024, 1048576}, 512);

    softmax_k<<<65536, 256>>>(s);

    // ctx = P @ V
    gemm128<<<dim3(4, 8, 64), 256>>>(
        FillTN{s, 1024, 1048576}, FillNN{v, 512, 524288},
        EpiStore{ctx, 512, 524288}, 1024);

    // x2 = xn + cat(ctx) @ Wo^T + bo    (in-place into xn buffer)
    gemm128<<<dim3(4, 64, 1), 256>>>(
        FillCat{ctx}, FillTN{Wo, 4096, 0}, EpiWo{xn, bo}, 4096);

    // rmsnorm #2 : x3 = scale * x2 / rms_batch(x2)
    reduce_sq_k<<<dim3(64, 8), 256>>>(xn, part);
    finalize_rms_k<<<8, 64>>>(part, inv);
    rmsnorm_k<<<4096, 256>>>(xn, scale, inv, x3);

    // FFN
    gemm128<<<dim3(4, 64, 1), 256>>>(
        FillTN{x3, 512, 0}, FillTN{Wff, 512, 0}, EpiBias{h1, bff, 512}, 512);
    gemm128<<<dim3(4, 64, 1), 256>>>(
        FillTN{h1, 512, 0}, FillTN{Wg, 512, 0}, EpiBias{gg, bg, 512}, 512);
    gemm128<<<dim3(4, 64, 1), 256>>>(
        FillTN{h1, 512, 0}, FillTN{Wl, 512, 0}, EpiBias{ll, bl, 512}, 512);

    // out = x3 + (g * sigmoid(beta*g)) * l
    swiglu_k<<<4096, 256>>>(x3, gg, ll, beta, out);
}